// round 9
// baseline (speedup 1.0000x reference)
#include <cuda_runtime.h>
#include <cuda_bf16.h>

// B=128, N=512, diagonals k=0..509 (offset k+1), len(k)=511-k.
// out = (loss[B], loss[B]).
//
// Quad scheme: aligned float4 at (row p, col 4m) has group j=4m-p (constant
// along p+=4); its elements lie on diagonals k_e=j+e-1. Thread owns jA and
// jB=507-jA; warp lanes -> one contiguous 512B LDG.128 per row. Loop bounds
// are PER-THREAD (p <= 508-j): short lanes predicate off, issuing no traffic,
// and every executed load is a fully-valid quad (no masking needed).
#define NN   512
#define KD   510
#define TPB  512
#define RSG  8          // grid row-split CTAs per batch -> 1024 CTAs total
#define RST  16         // total row splits (RSG * 2 in-CTA)
#define MAXB 160

__device__ float2 g_part[MAXB * RSG * 512];
__device__ int    g_count[MAXB];     // zero-init; reset by last CTA each replay

__global__ __launch_bounds__(TPB, 3)
void diag_quad(const float* __restrict__ S, float* __restrict__ out,
               int B, int out_size) {
    const int b    = blockIdx.x;
    const int rsg  = blockIdx.y;
    const int tid  = threadIdx.x;
    const int lane = tid & 31;
    const int w    = tid >> 5;       // 0..15
    const int rs   = w >> 3;         // in-CTA row split 0..1
    const int q    = w & 3;          // alignment class
    const int h    = (w >> 2) & 1;   // lane-half
    const int la   = h * 32 + lane;  // 0..63
    const int jA   = q - 2 + 4 * la;       // -2..253
    const int jB   = 509 - q - 4 * la;     // 509..254
    const int rst  = rsg * 2 + rs;         // 0..15

    const float* __restrict__ M = S + (size_t)b * NN * NN;

    float sA[4] = {0,0,0,0}, qA[4] = {0,0,0,0};
    float sB[4] = {0,0,0,0}, qB[4] = {0,0,0,0};

    // ---- side A: rows p ≡ (2-q) mod 4, col base p+jA (16B aligned)
    {
        int p = ((2 - q) & 3) + 4 * rst;
        const int pend = 508 - jA;               // per-thread exact bound
        const float* ptr = M + (size_t)p * (NN + 1) + jA;
        #pragma unroll 2
        for (; p <= pend; p += 4 * RST, ptr += 4 * RST * (NN + 1)) {
            float4 x = __ldcs((const float4*)ptr);
            sA[0] += x.x; qA[0] = fmaf(x.x, x.x, qA[0]);
            sA[1] += x.y; qA[1] = fmaf(x.y, x.y, qA[1]);
            sA[2] += x.z; qA[2] = fmaf(x.z, x.z, qA[2]);
            sA[3] += x.w; qA[3] = fmaf(x.w, x.w, qA[3]);
        }
    }
    // ---- side B: rows p ≡ (q+3) mod 4, col base p+jB (16B aligned)
    {
        int p = ((q + 3) & 3) + 4 * rst;
        const int pend = 508 - jB;               // per-thread exact bound
        const float* ptr = M + (size_t)p * (NN + 1) + jB;
        #pragma unroll 2
        for (; p <= pend; p += 4 * RST, ptr += 4 * RST * (NN + 1)) {
            float4 x = __ldcs((const float4*)ptr);
            sB[0] += x.x; qB[0] = fmaf(x.x, x.x, qB[0]);
            sB[1] += x.y; qB[1] = fmaf(x.y, x.y, qB[1]);
            sB[2] += x.z; qB[2] = fmaf(x.z, x.z, qB[2]);
            sB[3] += x.w; qB[3] = fmaf(x.w, x.w, qB[3]);
        }
    }

    // ---- deterministic (j,e) combine in smem: slot = j+2 in 0..511, one owner.
    __shared__ float psum[512][9];     // [slot][2e+stat], padded
    const int slotA = q + 4 * la;      // jA+2 : 0..255
    const int slotB = 511 - slotA;     // jB+2 : 256..511
    if (rs == 0) {
        #pragma unroll
        for (int e = 0; e < 4; ++e) {
            psum[slotA][2*e]   = sA[e];
            psum[slotA][2*e+1] = qA[e];
            psum[slotB][2*e]   = sB[e];
            psum[slotB][2*e+1] = qB[e];
        }
    }
    __syncthreads();
    if (rs == 1) {
        #pragma unroll
        for (int e = 0; e < 4; ++e) {
            psum[slotA][2*e]   += sA[e];
            psum[slotA][2*e+1] += qA[e];
            psum[slotB][2*e]   += sB[e];
            psum[slotB][2*e+1] += qB[e];
        }
    }
    __syncthreads();

    // ---- per-diag CTA partial: diag k <- (j=k+1-e, e), slot=k+3-e
    if (tid < KD) {
        float Ss = 0.f, Qs = 0.f;
        #pragma unroll
        for (int e = 0; e < 4; ++e) {
            int slot = tid + 3 - e;
            if (slot <= 511) { Ss += psum[slot][2*e]; Qs += psum[slot][2*e+1]; }
        }
        g_part[(b * RSG + rsg) * 512 + tid] = make_float2(Ss, Qs);
    }
    __threadfence();
    __syncthreads();

    __shared__ int is_last;
    if (tid == 0) {
        int old = atomicAdd(&g_count[b], 1);
        is_last = (old == RSG - 1);
        if (old == RSG - 1) g_count[b] = 0;   // reset for next graph replay
    }
    __syncthreads();

    if (is_last) {
        float contrib = 0.f;
        if (tid < KD) {
            float Ss = 0.f, Qs = 0.f;
            #pragma unroll
            for (int i = 0; i < RSG; ++i) {            // fixed order: deterministic
                float2 v = g_part[(b * RSG + i) * 512 + tid];
                Ss += v.x; Qs += v.y;
            }
            const float len = 511.0f - (float)tid;
            float mean = Ss / len;
            float var  = fmaxf((Qs - Ss * mean) / (len - 1.0f), 0.0f);
            contrib = sqrtf(var) * len * 0.2f;
        }
        __shared__ float red[TPB];
        red[tid] = contrib;
        __syncthreads();
        #pragma unroll
        for (int s = TPB / 2; s >= 32; s >>= 1) {
            if (tid < s) red[tid] += red[tid + s];
            __syncthreads();
        }
        if (tid < 32) {
            float v = red[tid];
            #pragma unroll
            for (int off = 16; off > 0; off >>= 1)
                v += __shfl_down_sync(0xFFFFFFFFu, v, off);
            if (tid == 0) {
                float loss = v / (float)KD;
                out[b] = loss;
                if (out_size >= 2 * B) out[B + b] = loss;
            }
        }
    }
}

extern "C" void kernel_launch(void* const* d_in, const int* in_sizes, int n_in,
                              void* d_out, int out_size) {
    const float* S = (const float*)d_in[0];
    float* out = (float*)d_out;
    const int B = in_sizes[0] / (NN * NN);
    dim3 grid(B, RSG);
    diag_quad<<<grid, TPB>>>(S, out, B, out_size);
}

// round 11
// speedup vs baseline: 1.2262x; 1.2262x over previous
#include <cuda_runtime.h>
#include <cuda_bf16.h>

// B=128, N=512, diagonals k=0..509 (offset k+1), len(k)=511-k.
// out = (loss[B], loss[B]).
//
// Quad scheme: aligned float4 at (row p, col 4m) has group j=4m-p (constant
// along p+=4); its elements lie on diagonals k_e=j+e-1. Thread owns jA and
// jB=507-jA; warp lanes -> one contiguous 512B LDG.128 per row. Loop bounds
// are PER-THREAD (p <= 508-j): lanes past their diagonal end predicate off
// and issue no memory traffic; every executed load is a fully-valid quad.
#define NN   512
#define KD   510
#define TPB  512
#define RSG  3          // grid row-split CTAs per batch (R8 geometry: proven)
#define RST  6          // total row splits (RSG * 2 in-CTA)
#define MAXB 256

__device__ float2 g_part[MAXB * RSG * 512];
__device__ int    g_count[MAXB];     // zero-init; reset by last CTA each replay

__global__ __launch_bounds__(TPB, 3)
void diag_quad(const float* __restrict__ S, float* __restrict__ out,
               int B, int out_size) {
    const int b    = blockIdx.x;
    const int rsg  = blockIdx.y;
    const int tid  = threadIdx.x;
    const int lane = tid & 31;
    const int w    = tid >> 5;       // 0..15
    const int rs   = w >> 3;         // in-CTA row split 0..1
    const int q    = w & 3;          // alignment class
    const int h    = (w >> 2) & 1;   // lane-half
    const int la   = h * 32 + lane;  // 0..63
    const int jA   = q - 2 + 4 * la;       // -2..253
    const int jB   = 509 - q - 4 * la;     // 509..254
    const int rst  = rsg * 2 + rs;         // 0..5

    const float* __restrict__ M = S + (size_t)b * NN * NN;

    float sA[4] = {0,0,0,0}, qA[4] = {0,0,0,0};
    float sB[4] = {0,0,0,0}, qB[4] = {0,0,0,0};

    // ---- side A: rows p ≡ (2-q) mod 4, col base p+jA (16B aligned)
    {
        int p = ((2 - q) & 3) + 4 * rst;
        const int pend = 508 - jA;               // per-thread exact bound
        const float* ptr = M + (size_t)p * (NN + 1) + jA;
        #pragma unroll 4
        for (; p <= pend; p += 4 * RST, ptr += 4 * RST * (NN + 1)) {
            float4 x = __ldcs((const float4*)ptr);
            sA[0] += x.x; qA[0] = fmaf(x.x, x.x, qA[0]);
            sA[1] += x.y; qA[1] = fmaf(x.y, x.y, qA[1]);
            sA[2] += x.z; qA[2] = fmaf(x.z, x.z, qA[2]);
            sA[3] += x.w; qA[3] = fmaf(x.w, x.w, qA[3]);
        }
    }
    // ---- side B: rows p ≡ (q+3) mod 4, col base p+jB (16B aligned)
    {
        int p = ((q + 3) & 3) + 4 * rst;
        const int pend = 508 - jB;               // per-thread exact bound
        const float* ptr = M + (size_t)p * (NN + 1) + jB;
        #pragma unroll 4
        for (; p <= pend; p += 4 * RST, ptr += 4 * RST * (NN + 1)) {
            float4 x = __ldcs((const float4*)ptr);
            sB[0] += x.x; qB[0] = fmaf(x.x, x.x, qB[0]);
            sB[1] += x.y; qB[1] = fmaf(x.y, x.y, qB[1]);
            sB[2] += x.z; qB[2] = fmaf(x.z, x.z, qB[2]);
            sB[3] += x.w; qB[3] = fmaf(x.w, x.w, qB[3]);
        }
    }

    // ---- deterministic (j,e) combine in smem: slot = j+2 in 0..511, one owner.
    __shared__ float psum[512][9];     // [slot][2e+stat], padded (stride 9 ⟂ 32 banks)
    const int slotA = q + 4 * la;      // jA+2 : 0..255
    const int slotB = 511 - slotA;     // jB+2 : 256..511
    if (rs == 0) {
        #pragma unroll
        for (int e = 0; e < 4; ++e) {
            psum[slotA][2*e]   = sA[e];
            psum[slotA][2*e+1] = qA[e];
            psum[slotB][2*e]   = sB[e];
            psum[slotB][2*e+1] = qB[e];
        }
    }
    __syncthreads();
    if (rs == 1) {
        #pragma unroll
        for (int e = 0; e < 4; ++e) {
            psum[slotA][2*e]   += sA[e];
            psum[slotA][2*e+1] += qA[e];
            psum[slotB][2*e]   += sB[e];
            psum[slotB][2*e+1] += qB[e];
        }
    }
    __syncthreads();

    // ---- per-diag CTA partial: diag k <- (j=k+1-e, e), slot=k+3-e
    if (tid < KD) {
        float Ss = 0.f, Qs = 0.f;
        #pragma unroll
        for (int e = 0; e < 4; ++e) {
            int slot = tid + 3 - e;
            if (slot <= 511) { Ss += psum[slot][2*e]; Qs += psum[slot][2*e+1]; }
        }
        g_part[(b * RSG + rsg) * 512 + tid] = make_float2(Ss, Qs);
    }
    __threadfence();
    __syncthreads();

    __shared__ int is_last;
    if (tid == 0) {
        int old = atomicAdd(&g_count[b], 1);
        is_last = (old == RSG - 1);
        if (old == RSG - 1) g_count[b] = 0;   // reset for next graph replay
    }
    __syncthreads();

    if (is_last) {
        float contrib = 0.f;
        if (tid < KD) {
            float Ss = 0.f, Qs = 0.f;
            #pragma unroll
            for (int i = 0; i < RSG; ++i) {            // fixed order: deterministic
                float2 v = g_part[(b * RSG + i) * 512 + tid];
                Ss += v.x; Qs += v.y;
            }
            const float len = 511.0f - (float)tid;
            float mean = Ss / len;
            float var  = fmaxf((Qs - Ss * mean) / (len - 1.0f), 0.0f);
            contrib = sqrtf(var) * len * 0.2f;
        }
        __shared__ float red[TPB];
        red[tid] = contrib;
        __syncthreads();
        #pragma unroll
        for (int s = TPB / 2; s >= 32; s >>= 1) {
            if (tid < s) red[tid] += red[tid + s];
            __syncthreads();
        }
        if (tid < 32) {
            float v = red[tid];
            #pragma unroll
            for (int off = 16; off > 0; off >>= 1)
                v += __shfl_down_sync(0xFFFFFFFFu, v, off);
            if (tid == 0) {
                float loss = v / (float)KD;
                out[b] = loss;
                if (out_size >= 2 * B) out[B + b] = loss;
            }
        }
    }
}

extern "C" void kernel_launch(void* const* d_in, const int* in_sizes, int n_in,
                              void* d_out, int out_size) {
    const float* S = (const float*)d_in[0];
    float* out = (float*)d_out;
    const int B = in_sizes[0] / (NN * NN);
    dim3 grid(B, RSG);
    diag_quad<<<grid, TPB>>>(S, out, B, out_size);
}